// round 12
// baseline (speedup 1.0000x reference)
#include <cuda_runtime.h>
#include <math.h>

#define BSZ 4
#define CC  4
#define NN  2048
#define DD  16
#define KK  32
#define MM  64
#define XF  256
#define FULLM 0xffffffffu
typedef unsigned long long ull;
#define INF32 0xffffffffu
#define INF64 0xFFFFFFFFFFFFFFFFull

// scratch (allocation-free rule: device globals)
__device__ int   g_nbr  [BSZ*CC*NN*KK];
__device__ float g_theta[BSZ*CC*NN*KK];
__device__ float g_gate [BSZ*CC*NN*KK];
__device__ float g_gsum [BSZ*CC*NN];
__device__ float g_awT  [128*MM];
__device__ float g_X    [BSZ*NN*XF];   // [b][n][ u'(128) | theta(128) ]

__device__ __forceinline__ ull warpmin64(ull p) {
    #pragma unroll
    for (int o = 16; o; o >>= 1) {
        ull q = __shfl_xor_sync(FULLM, p, o);
        if (q < p) p = q;
    }
    return p;
}

// bitonic compare-exchange (warp-wide, 2 elements/lane)
__device__ __forceinline__ float cexf(float v, int j, bool up, int lane) {
    float o = __shfl_xor_sync(FULLM, v, j);
    bool low = ((lane & j) == 0);
    float mn = fminf(v, o), mx = fmaxf(v, o);
    return (low == up) ? mn : mx;
}
__device__ __forceinline__ ull cex64(ull v, int j, bool up, int lane) {
    ull o = __shfl_xor_sync(FULLM, v, j);
    bool low = ((lane & j) == 0);
    ull mn = (v < o) ? v : o;
    ull mx = (v < o) ? o : v;
    return (low == up) ? mn : mx;
}

__device__ __forceinline__ void emit_row(
    int slice, int b, int i, unsigned nbd, int nbj,
    float Spos, const float* node_mask, const float4* spos, int lane)
{
    const float4 pi  = spos[i];
    const float mk   = node_mask[b*NN + i];
    const float dist = __uint_as_float(nbd);
    const int   nb   = nbj;

    const int nb0 = __shfl_sync(FULLM, nbj, 0);
    float4 pn0 = spos[nb0];
    float d0x = pn0.x - pi.x, d0y = pn0.y - pi.y, d0z = pn0.z - pi.z;
    float n0  = sqrtf(d0x*d0x + d0y*d0y + d0z*d0z);
    float inv0 = 1.f / fmaxf(n0, 1e-12f);
    d0x *= inv0; d0y *= inv0; d0z *= inv0;

    float cosv = 1.f;
    if (lane > 0) {
        float4 pn = spos[nb];
        float dx = pn.x - pi.x, dy = pn.y - pi.y, dz = pn.z - pi.z;
        float nrm = sqrtf(dx*dx + dy*dy + dz*dz);
        float inv = 1.f / fmaxf(nrm, 1e-12f);
        cosv = (dx*d0x + dy*d0y + dz*d0z) * inv;
    }
    const float gb   = fmaxf(dist * Spos, 0.f) * mk;
    const float gate = 1.f / (1.f + __expf(-gb));

    float G = gate;
    #pragma unroll
    for (int o = 16; o; o >>= 1) G += __shfl_xor_sync(FULLM, G, o);

    const size_t base = ((size_t)slice * NN + i) * KK;
    g_nbr  [base + lane] = nb;
    g_theta[base + lane] = cosv * mk;
    g_gate [base + lane] = gate;
    if (lane == 0) g_gsum[(size_t)slice*NN + i] = G;
}

// process one row's survivor buffer: sort 64 padded keys, ranks 1..32
__device__ __forceinline__ void select_row(
    int slice, int b, int i, const float4* spos, ull* row, int S,
    float Spos, const float* node_mask, int lane)
{
    unsigned nbd = 0; int nbj = 0;
    if (S <= 64) {
        ull V0 = row[lane], V1 = row[lane + 32];
        #pragma unroll
        for (int k = 2; k <= 32; k <<= 1) {
            #pragma unroll
            for (int j = k >> 1; j > 0; j >>= 1) {
                bool up0 = ((lane & k) == 0);
                bool up1 = (((lane + 32) & k) == 0);
                V0 = cex64(V0, j, up0, lane);
                V1 = cex64(V1, j, up1, lane);
            }
        }
        { ull lo = (V0 < V1) ? V0 : V1; ull hi = (V0 < V1) ? V1 : V0;
          V0 = lo; V1 = hi; }
        #pragma unroll
        for (int j = 16; j > 0; j >>= 1) {
            V0 = cex64(V0, j, true, lane);
            V1 = cex64(V1, j, true, lane);
        }
        ull a  = __shfl_sync(FULLM, V0, (lane + 1) & 31);
        ull bq = __shfl_sync(FULLM, V1, 0);
        ull kk = (lane == 31) ? bq : a;
        nbd = (unsigned)(kk >> 32); nbj = (int)(unsigned)kk;
    } else {
        // exact slow fallback (degenerate data only)
        const float4 pi = spos[i];
        ull last = 0;
        #pragma unroll 1
        for (int e = 0; e <= 32; e++) {
            ull best = INF64;
            for (int t = 0; t < 64; t++) {
                const int j = t*32 + lane;
                float4 pj = spos[j];
                float dot = fmaf(pi.z, pj.z, fmaf(pi.y, pj.y, pi.x * pj.x));
                float d   = fmaxf(fmaf(-2.f, dot, pj.w) + pi.w, 0.f);
                ull key = ((ull)__float_as_uint(d) << 32) | (unsigned)j;
                if ((e == 0 || key > last) && key < best) best = key;
            }
            ull wm = warpmin64(best);
            if (lane == e - 1) { nbd = (unsigned)(wm >> 32); nbj = (int)(unsigned)wm; }
            last = wm;
        }
    }
    emit_row(slice, b, i, nbd, nbj, Spos, node_mask, spos, lane);
}

// ---------------------------------------------------------------------------
// Kernel 1 v9.1 (unchanged): 2 rows/warp threshold select.
// ---------------------------------------------------------------------------
__global__ __launch_bounds__(512, 3) void knn_kernel(
    const float* __restrict__ pos, const float* __restrict__ node_mask,
    const float* __restrict__ rw1, const float* __restrict__ rw2,
    const float* __restrict__ aw)
{
    extern __shared__ char sm1[];
    float4* spos = (float4*)sm1;                       // 32KB
    ull*    srow = (ull*)(sm1 + NN*16);                // 32 rows x 64 = 16KB
    __shared__ int   scnt[32];
    __shared__ float sSpos;

    const int tid  = threadIdx.x;
    const int warp = tid >> 5;
    const int lane = tid & 31;
    const int slice = blockIdx.y;          // b*C + c
    const int b     = slice >> 2;
    const float* p  = pos + (size_t)slice * NN * 3;

    for (int j = tid; j < NN; j += 512) {
        float x = p[3*j], y = p[3*j+1], z = p[3*j+2];
        float q = fmaf(z, z, fmaf(y, y, x*x));
        spos[j] = make_float4(x, y, z, q);
    }

    // fold the aw transpose into one knn block (epilogue runs after knn)
    if (blockIdx.x == 0 && slice == 0) {
        for (int idx = tid; idx < 128*MM; idx += 512) {
            int f = idx >> 6, m = idx & 63;
            g_awT[idx] = aw[m*128 + f];
        }
    }

    // gate MLP collapses: relu(sum_m relu(d*w1)*w2) = relu(d*Spos) for d>=0
    if (tid < 32) {
        float a1 = rw1[tid],    w1v = rw2[tid];
        float a2 = rw1[tid+32], w2v = rw2[tid+32];
        float sp = fmaf(fmaxf(a1, 0.f), w1v, fmaxf(a2, 0.f) * w2v);
        #pragma unroll
        for (int o = 16; o; o >>= 1) sp += __shfl_xor_sync(FULLM, sp, o);
        if (tid == 0) sSpos = sp;
    }
    __syncthreads();

    const int iA = blockIdx.x * 32 + warp * 2;
    const int iB = iA + 1;
    const float4 piA = spos[iA];
    const float4 piB = spos[iB];

    // pass 1: per-lane two smallest d per row (floats, FMNMX; no indices)
    float a0 = INFINITY, a1 = INFINITY;
    float b0 = INFINITY, b1 = INFINITY;
    #pragma unroll 4
    for (int t = 0; t < 64; t++) {
        float4 pj = spos[t*32 + lane];
        float dotA = fmaf(piA.z, pj.z, fmaf(piA.y, pj.y, piA.x * pj.x));
        float dA   = fmaf(-2.f, dotA, pj.w) + piA.w;
        float tA = fmaxf(a0, dA); a0 = fminf(a0, dA); a1 = fminf(a1, tA);
        float dotB = fmaf(piB.z, pj.z, fmaf(piB.y, pj.y, piB.x * pj.x));
        float dB   = fmaf(-2.f, dotB, pj.w) + piB.w;
        float tB = fmaxf(b0, dB); b0 = fminf(b0, dB); b1 = fminf(b1, tB);
    }

    // bitonic sort 64 heads per row (2 rows interleaved); T = rank 32
    float TA, TB;
    {
        float vA0 = a0, vA1 = a1, vB0 = b0, vB1 = b1;
        #pragma unroll
        for (int k = 2; k <= 32; k <<= 1) {
            #pragma unroll
            for (int j = k >> 1; j > 0; j >>= 1) {
                bool up0 = ((lane & k) == 0);
                bool up1 = (((lane + 32) & k) == 0);
                vA0 = cexf(vA0, j, up0, lane);
                vA1 = cexf(vA1, j, up1, lane);
                vB0 = cexf(vB0, j, up0, lane);
                vB1 = cexf(vB1, j, up1, lane);
            }
        }
        { float lo = fminf(vA0, vA1), hi = fmaxf(vA0, vA1); vA0 = lo; vA1 = hi; }
        { float lo = fminf(vB0, vB1), hi = fmaxf(vB0, vB1); vB0 = lo; vB1 = hi; }
        #pragma unroll
        for (int j = 16; j > 0; j >>= 1) {
            vA0 = cexf(vA0, j, true, lane);
            vA1 = cexf(vA1, j, true, lane);
            vB0 = cexf(vB0, j, true, lane);
            vB1 = cexf(vB1, j, true, lane);
        }
        TA = __shfl_sync(FULLM, vA1, 0);
        TB = __shfl_sync(FULLM, vB1, 0);
    }

    // init survivor buffers
    ull* rowA = srow + (warp*2    ) * 64;
    ull* rowB = srow + (warp*2 + 1) * 64;
    if (lane == 0) { scnt[warp*2] = 0; scnt[warp*2+1] = 0; }
    rowA[lane] = INF64; rowA[lane+32] = INF64;
    rowB[lane] = INF64; rowB[lane+32] = INF64;
    __syncwarp();

    // pass 2: compact survivors (d <= T), shared pj loads
    #pragma unroll 4
    for (int t = 0; t < 64; t++) {
        const int j = t*32 + lane;
        float4 pj = spos[j];
        float dotA = fmaf(piA.z, pj.z, fmaf(piA.y, pj.y, piA.x * pj.x));
        float dA   = fmaf(-2.f, dotA, pj.w) + piA.w;
        if (dA <= TA) {
            unsigned u = __float_as_uint(fmaxf(dA, 0.f));
            int idx = atomicAdd(&scnt[warp*2], 1);
            if (idx < 64) rowA[idx] = ((ull)u << 32) | (unsigned)j;
        }
        float dotB = fmaf(piB.z, pj.z, fmaf(piB.y, pj.y, piB.x * pj.x));
        float dB   = fmaf(-2.f, dotB, pj.w) + piB.w;
        if (dB <= TB) {
            unsigned u = __float_as_uint(fmaxf(dB, 0.f));
            int idx = atomicAdd(&scnt[warp*2+1], 1);
            if (idx < 64) rowB[idx] = ((ull)u << 32) | (unsigned)j;
        }
    }
    __syncwarp();

    const float Spos = sSpos;
    select_row(slice, b, iA, spos, rowA, scnt[warp*2],   Spos, node_mask, lane);
    select_row(slice, b, iB, spos, rowB, scnt[warp*2+1], Spos, node_mask, lane);
}

// ---------------------------------------------------------------------------
// Kernel 2a: gather. One (b,c) slice per block (L1-resident features).
// Grid (32 chunks of 64 nodes, 16 slices), block 256 = (node, quarter).
// Writes g_X[b][n][256] = [u'(128, pre-masked) | theta(128)].
// ---------------------------------------------------------------------------
__global__ __launch_bounds__(256) void gather_kernel(
    const float* __restrict__ node_fea, const float* __restrict__ node_mask)
{
    const int slice = blockIdx.y;          // b*C + c
    const int b = slice >> 2, c = slice & 3;
    const int tid = threadIdx.x;
    const int n = tid >> 2, q = tid & 3;   // 4 lanes per node: 64B coalesced
    const int node = blockIdx.x * 64 + n;

    const float* nf = node_fea + (size_t)slice * NN * DD;
    const float mk = node_mask[b*NN + node];
    const float G  = g_gsum[(size_t)slice*NN + node];
    const size_t eb = ((size_t)slice*NN + node) * KK;

    float4 acc = {0.f, 0.f, 0.f, 0.f};
    #pragma unroll 4
    for (int k4 = 0; k4 < 8; k4++) {
        float4 g4 = __ldg((const float4*)(g_gate + eb) + k4);
        int4   n4 = __ldg((const int4*)  (g_nbr  + eb) + k4);
        const float gs[4] = {g4.x, g4.y, g4.z, g4.w};
        const int   ns[4] = {n4.x, n4.y, n4.z, n4.w};
        #pragma unroll
        for (int e = 0; e < 4; e++) {
            float4 v = __ldg((const float4*)(nf + (size_t)ns[e]*DD) + q);
            acc.x = fmaf(gs[e], v.x, acc.x); acc.y = fmaf(gs[e], v.y, acc.y);
            acc.z = fmaf(gs[e], v.z, acc.z); acc.w = fmaf(gs[e], v.w, acc.w);
        }
    }

    float* X = g_X + ((size_t)b*NN + node) * XF;
    // neighbor block: f = c*32 + 16 + q*4
    *(float4*)(X + c*32 + 16 + q*4) =
        make_float4(acc.x*mk, acc.y*mk, acc.z*mk, acc.w*mk);
    // self block: f = c*32 + q*4
    float4 fv = __ldg((const float4*)(nf + (size_t)node*DD) + q);
    const float Gm = G * mk;
    *(float4*)(X + c*32 + q*4) =
        make_float4(Gm*fv.x, Gm*fv.y, Gm*fv.z, Gm*fv.w);
    // theta: f = 128 + k*4 + c, this thread covers k = q*8 .. q*8+7
    float4 t0 = __ldg((const float4*)(g_theta + eb) + q*2);
    float4 t1 = __ldg((const float4*)(g_theta + eb) + q*2 + 1);
    float* XT = X + 128 + q*32 + c;
    XT[ 0] = t0.x; XT[ 4] = t0.y; XT[ 8] = t0.z; XT[12] = t0.w;
    XT[16] = t1.x; XT[20] = t1.y; XT[24] = t1.z; XT[28] = t1.w;
}

// ---------------------------------------------------------------------------
// Kernel 2b: GEMM. out[b][m][n] = leaky(Wstack^T @ X)·mask.
// Wstack[256][64] = [sw ; awT] staged once in smem; X tile [256][32] staged
// coalesced. Grid 256 (4b x 64 n-chunks of 32), block 256, tile 4m x 2n.
// ---------------------------------------------------------------------------
#define GX_PIT 34
#define GEMM_SMEM ((16384 + 256*GX_PIT) * 4)

__global__ __launch_bounds__(256) void gemm_kernel(
    const float* __restrict__ sw, const float* __restrict__ node_mask,
    float* __restrict__ out)
{
    extern __shared__ float sm[];
    float* sW = sm;                        // [256 f][64 m]
    float* sX = sm + 16384;                // [256 f][n pitch 34]

    const int tid = threadIdx.x;
    const int b   = blockIdx.x >> 6;
    const int n0  = (blockIdx.x & 63) * 32;

    for (int idx = tid; idx < 16384; idx += 256)
        sW[idx] = (idx < 8192) ? sw[idx] : g_awT[idx - 8192];

    for (int idx = tid; idx < 2048; idx += 256) {
        int fq = idx & 63, n = idx >> 6;
        float4 v = *(const float4*)(g_X + ((size_t)b*NN + n0 + n)*XF + fq*4);
        int f = fq * 4;
        sX[(f+0)*GX_PIT + n] = v.x;  sX[(f+1)*GX_PIT + n] = v.y;
        sX[(f+2)*GX_PIT + n] = v.z;  sX[(f+3)*GX_PIT + n] = v.w;
    }
    __syncthreads();

    const int mg = (tid & 15) * 4;
    const int ng = tid >> 4;               // n = ng*2 + {0,1}
    float acc[4][2];
    #pragma unroll
    for (int a = 0; a < 4; a++) { acc[a][0] = 0.f; acc[a][1] = 0.f; }

    #pragma unroll 8
    for (int f = 0; f < XF; f++) {
        float4 w = *(const float4*)&sW[f*64 + mg];
        float2 x = *(const float2*)&sX[f*GX_PIT + ng*2];
        acc[0][0] = fmaf(w.x, x.x, acc[0][0]); acc[0][1] = fmaf(w.x, x.y, acc[0][1]);
        acc[1][0] = fmaf(w.y, x.x, acc[1][0]); acc[1][1] = fmaf(w.y, x.y, acc[1][1]);
        acc[2][0] = fmaf(w.z, x.x, acc[2][0]); acc[2][1] = fmaf(w.z, x.y, acc[2][1]);
        acc[3][0] = fmaf(w.w, x.x, acc[3][0]); acc[3][1] = fmaf(w.w, x.y, acc[3][1]);
    }

    const float mk0 = node_mask[b*NN + n0 + ng*2];
    const float mk1 = node_mask[b*NN + n0 + ng*2 + 1];
    #pragma unroll
    for (int a = 0; a < 4; a++) {
        float v0 = acc[a][0], v1 = acc[a][1];
        v0 = (v0 >= 0.f) ? v0 : 0.01f*v0;
        v1 = (v1 >= 0.f) ? v1 : 0.01f*v1;
        float2 o2 = make_float2(v0*mk0, v1*mk1);
        *(float2*)&out[((size_t)b*MM + mg + a)*NN + n0 + ng*2] = o2;
    }
}

// ---------------------------------------------------------------------------
extern "C" void kernel_launch(void* const* d_in, const int* in_sizes, int n_in,
                              void* d_out, int out_size)
{
    const float* pos       = (const float*)d_in[0];
    const float* node_fea  = (const float*)d_in[1];
    const float* node_mask = (const float*)d_in[2];
    const float* aw        = (const float*)d_in[3];
    const float* sw        = (const float*)d_in[4];
    const float* rw1       = (const float*)d_in[5];
    const float* rw2       = (const float*)d_in[6];
    float* out = (float*)d_out;

    const int smem1 = NN*16 + 32*64*8;     // 49152
    cudaFuncSetAttribute(knn_kernel,
        cudaFuncAttributeMaxDynamicSharedMemorySize, smem1);
    cudaFuncSetAttribute(gemm_kernel,
        cudaFuncAttributeMaxDynamicSharedMemorySize, GEMM_SMEM);

    knn_kernel<<<dim3(NN/32, BSZ*CC), 512, smem1>>>(pos, node_mask, rw1, rw2, aw);
    gather_kernel<<<dim3(NN/64, BSZ*CC), 256>>>(node_fea, node_mask);
    gemm_kernel<<<BSZ*(NN/32), 256, GEMM_SMEM>>>(sw, node_mask, out);
}

// round 13
// speedup vs baseline: 1.0836x; 1.0836x over previous
#include <cuda_runtime.h>
#include <math.h>

#define BSZ 4
#define CC  4
#define NN  2048
#define DD  16
#define KK  32
#define MM  64
#define XF  256
#define FULLM 0xffffffffu
typedef unsigned long long ull;
#define INF64 0xFFFFFFFFFFFFFFFFull

// scratch (allocation-free rule: device globals)
__device__ float g_awT  [128*MM];
__device__ float g_X    [BSZ*NN*XF];   // [b][n][ u'(128) | theta(128) ]

__device__ __forceinline__ ull warpmin64(ull p) {
    #pragma unroll
    for (int o = 16; o; o >>= 1) {
        ull q = __shfl_xor_sync(FULLM, p, o);
        if (q < p) p = q;
    }
    return p;
}

// bitonic compare-exchange (warp-wide, 2 elements/lane)
__device__ __forceinline__ float cexf(float v, int j, bool up, int lane) {
    float o = __shfl_xor_sync(FULLM, v, j);
    bool low = ((lane & j) == 0);
    float mn = fminf(v, o), mx = fmaxf(v, o);
    return (low == up) ? mn : mx;
}
__device__ __forceinline__ ull cex64(ull v, int j, bool up, int lane) {
    ull o = __shfl_xor_sync(FULLM, v, j);
    bool low = ((lane & j) == 0);
    ull mn = (v < o) ? v : o;
    ull mx = (v < o) ? o : v;
    return (low == up) ? mn : mx;
}

// sort one row's survivor buffer (64 padded keys); return rank lane+1
__device__ __forceinline__ void select_row(
    int i, const float4* spos, ull* row, int S, int lane,
    unsigned& nbd, int& nbj)
{
    nbd = 0; nbj = 0;
    if (S <= 64) {
        ull V0 = row[lane], V1 = row[lane + 32];
        #pragma unroll
        for (int k = 2; k <= 32; k <<= 1) {
            #pragma unroll
            for (int j = k >> 1; j > 0; j >>= 1) {
                bool up0 = ((lane & k) == 0);
                bool up1 = (((lane + 32) & k) == 0);
                V0 = cex64(V0, j, up0, lane);
                V1 = cex64(V1, j, up1, lane);
            }
        }
        { ull lo = (V0 < V1) ? V0 : V1; ull hi = (V0 < V1) ? V1 : V0;
          V0 = lo; V1 = hi; }
        #pragma unroll
        for (int j = 16; j > 0; j >>= 1) {
            V0 = cex64(V0, j, true, lane);
            V1 = cex64(V1, j, true, lane);
        }
        ull a  = __shfl_sync(FULLM, V0, (lane + 1) & 31);
        ull bq = __shfl_sync(FULLM, V1, 0);
        ull kk = (lane == 31) ? bq : a;
        nbd = (unsigned)(kk >> 32); nbj = (int)(unsigned)kk;
    } else {
        // exact slow fallback (degenerate data only)
        const float4 pi = spos[i];
        ull last = 0;
        #pragma unroll 1
        for (int e = 0; e <= 32; e++) {
            ull best = INF64;
            for (int t = 0; t < 64; t++) {
                const int j = t*32 + lane;
                float4 pj = spos[j];
                float dot = fmaf(pi.z, pj.z, fmaf(pi.y, pj.y, pi.x * pj.x));
                float d   = fmaxf(fmaf(-2.f, dot, pj.w) + pi.w, 0.f);
                ull key = ((ull)__float_as_uint(d) << 32) | (unsigned)j;
                if ((e == 0 || key > last) && key < best) best = key;
            }
            ull wm = warpmin64(best);
            if (lane == e - 1) { nbd = (unsigned)(wm >> 32); nbj = (int)(unsigned)wm; }
            last = wm;
        }
    }
}

// compute theta/gate for one row, store theta to g_X, stash (gate,nb) pairs
__device__ __forceinline__ void emit_stash(
    int c, int b, int i, unsigned nbd, int nbj, float Spos,
    const float* node_mask, const float4* spos, int lane,
    ull* pair, float& Gout, float& mkout)
{
    const float4 pi  = spos[i];
    const float mk   = node_mask[b*NN + i];
    const float dist = __uint_as_float(nbd);
    const int   nb   = nbj;

    const int nb0 = __shfl_sync(FULLM, nbj, 0);
    float4 pn0 = spos[nb0];
    float d0x = pn0.x - pi.x, d0y = pn0.y - pi.y, d0z = pn0.z - pi.z;
    float n0  = sqrtf(d0x*d0x + d0y*d0y + d0z*d0z);
    float inv0 = 1.f / fmaxf(n0, 1e-12f);
    d0x *= inv0; d0y *= inv0; d0z *= inv0;

    float cosv = 1.f;
    if (lane > 0) {
        float4 pn = spos[nb];
        float dx = pn.x - pi.x, dy = pn.y - pi.y, dz = pn.z - pi.z;
        float nrm = sqrtf(dx*dx + dy*dy + dz*dz);
        float inv = 1.f / fmaxf(nrm, 1e-12f);
        cosv = (dx*d0x + dy*d0y + dz*d0z) * inv;
    }
    const float gb   = fmaxf(dist * Spos, 0.f) * mk;
    const float gate = 1.f / (1.f + __expf(-gb));

    float G = gate;
    #pragma unroll
    for (int o = 16; o; o >>= 1) G += __shfl_xor_sync(FULLM, G, o);

    // theta: f = lane*4 + c
    g_X[((size_t)b*NN + i)*XF + 128 + lane*4 + c] = cosv * mk;
    pair[lane] = ((ull)__float_as_uint(gate) << 32) | (unsigned)nb;
    Gout = G; mkout = mk;
}

// ---------------------------------------------------------------------------
// Kernel 1 v10: 2 rows/warp threshold select (shifted s = d - q_i) with the
// feature gather folded into the epilogue. Writes g_X directly.
// 48KB dyn smem, occ 3.
// ---------------------------------------------------------------------------
__global__ __launch_bounds__(512, 3) void knn_kernel(
    const float* __restrict__ pos, const float* __restrict__ node_fea,
    const float* __restrict__ node_mask,
    const float* __restrict__ rw1, const float* __restrict__ rw2,
    const float* __restrict__ aw)
{
    extern __shared__ char sm1[];
    float4* spos = (float4*)sm1;                       // 32KB
    ull*    srow = (ull*)(sm1 + NN*16);                // 32 rows x 64 = 16KB
    __shared__ int   scnt[32];
    __shared__ float sSpos;

    const int tid  = threadIdx.x;
    const int warp = tid >> 5;
    const int lane = tid & 31;
    const int slice = blockIdx.y;          // b*C + c
    const int b     = slice >> 2;
    const int c     = slice & 3;
    const float* p  = pos + (size_t)slice * NN * 3;
    const float* nf = node_fea + (size_t)slice * NN * DD;

    for (int j = tid; j < NN; j += 512) {
        float x = p[3*j], y = p[3*j+1], z = p[3*j+2];
        float q = fmaf(z, z, fmaf(y, y, x*x));
        spos[j] = make_float4(x, y, z, q);
    }

    // fold the aw transpose into one knn block (gemm runs after knn)
    if (blockIdx.x == 0 && slice == 0) {
        for (int idx = tid; idx < 128*MM; idx += 512) {
            int f = idx >> 6, m = idx & 63;
            g_awT[idx] = aw[m*128 + f];
        }
    }

    // gate MLP collapses: relu(sum_m relu(d*w1)*w2) = relu(d*Spos) for d>=0
    if (tid < 32) {
        float a1 = rw1[tid],    w1v = rw2[tid];
        float a2 = rw1[tid+32], w2v = rw2[tid+32];
        float sp = fmaf(fmaxf(a1, 0.f), w1v, fmaxf(a2, 0.f) * w2v);
        #pragma unroll
        for (int o = 16; o; o >>= 1) sp += __shfl_xor_sync(FULLM, sp, o);
        if (tid == 0) sSpos = sp;
    }
    __syncthreads();

    const int iA = blockIdx.x * 32 + warp * 2;
    const int iB = iA + 1;
    const float4 piA = spos[iA];
    const float4 piB = spos[iB];

    // pass 1: per-lane two smallest s = -2*dot + q_j (order == d order)
    float a0 = INFINITY, a1 = INFINITY;
    float b0 = INFINITY, b1 = INFINITY;
    #pragma unroll 4
    for (int t = 0; t < 64; t++) {
        float4 pj = spos[t*32 + lane];
        float dotA = fmaf(piA.z, pj.z, fmaf(piA.y, pj.y, piA.x * pj.x));
        float sA   = fmaf(-2.f, dotA, pj.w);
        float tA = fmaxf(a0, sA); a0 = fminf(a0, sA); a1 = fminf(a1, tA);
        float dotB = fmaf(piB.z, pj.z, fmaf(piB.y, pj.y, piB.x * pj.x));
        float sB   = fmaf(-2.f, dotB, pj.w);
        float tB = fmaxf(b0, sB); b0 = fminf(b0, sB); b1 = fminf(b1, tB);
    }

    // bitonic sort 64 heads per row (2 rows interleaved); T = rank 32
    float TA, TB;
    {
        float vA0 = a0, vA1 = a1, vB0 = b0, vB1 = b1;
        #pragma unroll
        for (int k = 2; k <= 32; k <<= 1) {
            #pragma unroll
            for (int j = k >> 1; j > 0; j >>= 1) {
                bool up0 = ((lane & k) == 0);
                bool up1 = (((lane + 32) & k) == 0);
                vA0 = cexf(vA0, j, up0, lane);
                vA1 = cexf(vA1, j, up1, lane);
                vB0 = cexf(vB0, j, up0, lane);
                vB1 = cexf(vB1, j, up1, lane);
            }
        }
        { float lo = fminf(vA0, vA1), hi = fmaxf(vA0, vA1); vA0 = lo; vA1 = hi; }
        { float lo = fminf(vB0, vB1), hi = fmaxf(vB0, vB1); vB0 = lo; vB1 = hi; }
        #pragma unroll
        for (int j = 16; j > 0; j >>= 1) {
            vA0 = cexf(vA0, j, true, lane);
            vA1 = cexf(vA1, j, true, lane);
            vB0 = cexf(vB0, j, true, lane);
            vB1 = cexf(vB1, j, true, lane);
        }
        TA = __shfl_sync(FULLM, vA1, 0);
        TB = __shfl_sync(FULLM, vB1, 0);
    }

    // init survivor buffers
    ull* rowA = srow + (warp*2    ) * 64;
    ull* rowB = srow + (warp*2 + 1) * 64;
    if (lane == 0) { scnt[warp*2] = 0; scnt[warp*2+1] = 0; }
    rowA[lane] = INF64; rowA[lane+32] = INF64;
    rowB[lane] = INF64; rowB[lane+32] = INF64;
    __syncwarp();

    // pass 2: compact survivors (s <= T); key stores d = max(s + q_i, 0)
    #pragma unroll 4
    for (int t = 0; t < 64; t++) {
        const int j = t*32 + lane;
        float4 pj = spos[j];
        float dotA = fmaf(piA.z, pj.z, fmaf(piA.y, pj.y, piA.x * pj.x));
        float sA   = fmaf(-2.f, dotA, pj.w);
        if (sA <= TA) {
            unsigned u = __float_as_uint(fmaxf(sA + piA.w, 0.f));
            int idx = atomicAdd(&scnt[warp*2], 1);
            if (idx < 64) rowA[idx] = ((ull)u << 32) | (unsigned)j;
        }
        float dotB = fmaf(piB.z, pj.z, fmaf(piB.y, pj.y, piB.x * pj.x));
        float sB   = fmaf(-2.f, dotB, pj.w);
        if (sB <= TB) {
            unsigned u = __float_as_uint(fmaxf(sB + piB.w, 0.f));
            int idx = atomicAdd(&scnt[warp*2+1], 1);
            if (idx < 64) rowB[idx] = ((ull)u << 32) | (unsigned)j;
        }
    }
    __syncwarp();

    unsigned nbdA, nbdB; int nbjA, nbjB;
    select_row(iA, spos, rowA, scnt[warp*2],   lane, nbdA, nbjA);
    select_row(iB, spos, rowB, scnt[warp*2+1], lane, nbdB, nbjB);

    // epilogue: theta + gate, stash pairs, fold the feature gather
    const float Spos = sSpos;
    float GA, mkA, GB, mkB;
    emit_stash(c, b, iA, nbdA, nbjA, Spos, node_mask, spos, lane, rowA, GA, mkA);
    emit_stash(c, b, iB, nbdB, nbjB, Spos, node_mask, spos, lane, rowB, GB, mkB);
    __syncwarp();

    {
        const int row = lane >> 4, t = lane & 15;
        const int i   = row ? iB : iA;
        const ull* pr = row ? rowB : rowA;
        float acc = 0.f;
        #pragma unroll 8
        for (int k = 0; k < KK; k++) {
            ull pk = pr[k];
            float g = __uint_as_float((unsigned)(pk >> 32));
            int  nb = (int)(unsigned)pk;
            acc = fmaf(g, __ldg(nf + nb*DD + t), acc);
        }
        const float G  = row ? GB : GA;
        const float mk = row ? mkB : mkA;
        float selfv = __ldg(nf + (size_t)i*DD + t);
        float* gx = g_X + ((size_t)b*NN + i)*XF + c*32;
        gx[t]      = G * mk * selfv;   // self block
        gx[16 + t] = acc * mk;         // neighbor block
    }
}

// ---------------------------------------------------------------------------
// Kernel 2 (R12 exact): GEMM. out[b][m][n] = leaky(Wstack^T @ X)·mask.
// ---------------------------------------------------------------------------
#define GX_PIT 34
#define GEMM_SMEM ((16384 + 256*GX_PIT) * 4)

__global__ __launch_bounds__(256) void gemm_kernel(
    const float* __restrict__ sw, const float* __restrict__ node_mask,
    float* __restrict__ out)
{
    extern __shared__ float sm[];
    float* sW = sm;                        // [256 f][64 m]
    float* sX = sm + 16384;                // [256 f][n pitch 34]

    const int tid = threadIdx.x;
    const int b   = blockIdx.x >> 6;
    const int n0  = (blockIdx.x & 63) * 32;

    for (int idx = tid; idx < 16384; idx += 256)
        sW[idx] = (idx < 8192) ? sw[idx] : g_awT[idx - 8192];

    for (int idx = tid; idx < 2048; idx += 256) {
        int fq = idx & 63, n = idx >> 6;
        float4 v = *(const float4*)(g_X + ((size_t)b*NN + n0 + n)*XF + fq*4);
        int f = fq * 4;
        sX[(f+0)*GX_PIT + n] = v.x;  sX[(f+1)*GX_PIT + n] = v.y;
        sX[(f+2)*GX_PIT + n] = v.z;  sX[(f+3)*GX_PIT + n] = v.w;
    }
    __syncthreads();

    const int mg = (tid & 15) * 4;
    const int ng = tid >> 4;               // n = ng*2 + {0,1}
    float acc[4][2];
    #pragma unroll
    for (int a = 0; a < 4; a++) { acc[a][0] = 0.f; acc[a][1] = 0.f; }

    #pragma unroll 8
    for (int f = 0; f < XF; f++) {
        float4 w = *(const float4*)&sW[f*64 + mg];
        float2 x = *(const float2*)&sX[f*GX_PIT + ng*2];
        acc[0][0] = fmaf(w.x, x.x, acc[0][0]); acc[0][1] = fmaf(w.x, x.y, acc[0][1]);
        acc[1][0] = fmaf(w.y, x.x, acc[1][0]); acc[1][1] = fmaf(w.y, x.y, acc[1][1]);
        acc[2][0] = fmaf(w.z, x.x, acc[2][0]); acc[2][1] = fmaf(w.z, x.y, acc[2][1]);
        acc[3][0] = fmaf(w.w, x.x, acc[3][0]); acc[3][1] = fmaf(w.w, x.y, acc[3][1]);
    }

    const float mk0 = node_mask[b*NN + n0 + ng*2];
    const float mk1 = node_mask[b*NN + n0 + ng*2 + 1];
    #pragma unroll
    for (int a = 0; a < 4; a++) {
        float v0 = acc[a][0], v1 = acc[a][1];
        v0 = (v0 >= 0.f) ? v0 : 0.01f*v0;
        v1 = (v1 >= 0.f) ? v1 : 0.01f*v1;
        float2 o2 = make_float2(v0*mk0, v1*mk1);
        *(float2*)&out[((size_t)b*MM + mg + a)*NN + n0 + ng*2] = o2;
    }
}

// ---------------------------------------------------------------------------
extern "C" void kernel_launch(void* const* d_in, const int* in_sizes, int n_in,
                              void* d_out, int out_size)
{
    const float* pos       = (const float*)d_in[0];
    const float* node_fea  = (const float*)d_in[1];
    const float* node_mask = (const float*)d_in[2];
    const float* aw        = (const float*)d_in[3];
    const float* sw        = (const float*)d_in[4];
    const float* rw1       = (const float*)d_in[5];
    const float* rw2       = (const float*)d_in[6];
    float* out = (float*)d_out;

    const int smem1 = NN*16 + 32*64*8;     // 49152
    cudaFuncSetAttribute(knn_kernel,
        cudaFuncAttributeMaxDynamicSharedMemorySize, smem1);
    cudaFuncSetAttribute(gemm_kernel,
        cudaFuncAttributeMaxDynamicSharedMemorySize, GEMM_SMEM);

    knn_kernel<<<dim3(NN/32, BSZ*CC), 512, smem1>>>(
        pos, node_fea, node_mask, rw1, rw2, aw);
    gemm_kernel<<<BSZ*(NN/32), 256, GEMM_SMEM>>>(sw, node_mask, out);
}

// round 14
// speedup vs baseline: 1.0947x; 1.0103x over previous
#include <cuda_runtime.h>
#include <math.h>

#define BSZ 4
#define CC  4
#define NN  2048
#define DD  16
#define KK  32
#define MM  64
#define XF  256
#define FULLM 0xffffffffu
typedef unsigned long long ull;
#define INF64 0xFFFFFFFFFFFFFFFFull

// scratch (allocation-free rule: device globals)
__device__ float g_awT  [128*MM];
__device__ float g_X    [BSZ*NN*XF];   // [b][n][ u'(128) | theta(128) ]

__device__ __forceinline__ ull warpmin64(ull p) {
    #pragma unroll
    for (int o = 16; o; o >>= 1) {
        ull q = __shfl_xor_sync(FULLM, p, o);
        if (q < p) p = q;
    }
    return p;
}

// bitonic compare-exchange (warp-wide, 2 elements/lane)
__device__ __forceinline__ float cexf(float v, int j, bool up, int lane) {
    float o = __shfl_xor_sync(FULLM, v, j);
    bool low = ((lane & j) == 0);
    float mn = fminf(v, o), mx = fmaxf(v, o);
    return (low == up) ? mn : mx;
}
__device__ __forceinline__ ull cex64(ull v, int j, bool up, int lane) {
    ull o = __shfl_xor_sync(FULLM, v, j);
    bool low = ((lane & j) == 0);
    ull mn = (v < o) ? v : o;
    ull mx = (v < o) ? o : v;
    return (low == up) ? mn : mx;
}

// sort one row's survivor buffer (64 padded keys); return rank lane+1
__device__ __forceinline__ void select_row(
    int i, const float4* spos, ull* row, int S, int lane,
    unsigned& nbd, int& nbj)
{
    nbd = 0; nbj = 0;
    if (S <= 64) {
        ull V0 = row[lane], V1 = row[lane + 32];
        #pragma unroll
        for (int k = 2; k <= 32; k <<= 1) {
            #pragma unroll
            for (int j = k >> 1; j > 0; j >>= 1) {
                bool up0 = ((lane & k) == 0);
                bool up1 = (((lane + 32) & k) == 0);
                V0 = cex64(V0, j, up0, lane);
                V1 = cex64(V1, j, up1, lane);
            }
        }
        { ull lo = (V0 < V1) ? V0 : V1; ull hi = (V0 < V1) ? V1 : V0;
          V0 = lo; V1 = hi; }
        #pragma unroll
        for (int j = 16; j > 0; j >>= 1) {
            V0 = cex64(V0, j, true, lane);
            V1 = cex64(V1, j, true, lane);
        }
        ull a  = __shfl_sync(FULLM, V0, (lane + 1) & 31);
        ull bq = __shfl_sync(FULLM, V1, 0);
        ull kk = (lane == 31) ? bq : a;
        nbd = (unsigned)(kk >> 32); nbj = (int)(unsigned)kk;
    } else {
        // exact slow fallback (degenerate data only)
        const float4 pi = spos[i];
        ull last = 0;
        #pragma unroll 1
        for (int e = 0; e <= 32; e++) {
            ull best = INF64;
            for (int t = 0; t < 64; t++) {
                const int j = t*32 + lane;
                float4 pj = spos[j];
                float dot = fmaf(pi.z, pj.z, fmaf(pi.y, pj.y, pi.x * pj.x));
                float d   = fmaxf(fmaf(-2.f, dot, pj.w) + pi.w, 0.f);
                ull key = ((ull)__float_as_uint(d) << 32) | (unsigned)j;
                if ((e == 0 || key > last) && key < best) best = key;
            }
            ull wm = warpmin64(best);
            if (lane == e - 1) { nbd = (unsigned)(wm >> 32); nbj = (int)(unsigned)wm; }
            last = wm;
        }
    }
}

// compute theta/gate for one row, store theta to g_X, stash (gate,nb) pairs
__device__ __forceinline__ void emit_stash(
    int c, int b, int i, unsigned nbd, int nbj, float Spos,
    const float* node_mask, const float4* spos, int lane,
    ull* pair, float& Gout, float& mkout)
{
    const float4 pi  = spos[i];
    const float mk   = node_mask[b*NN + i];
    const float dist = __uint_as_float(nbd);
    const int   nb   = nbj;

    const int nb0 = __shfl_sync(FULLM, nbj, 0);
    float4 pn0 = spos[nb0];
    float d0x = pn0.x - pi.x, d0y = pn0.y - pi.y, d0z = pn0.z - pi.z;
    float n0  = sqrtf(d0x*d0x + d0y*d0y + d0z*d0z);
    float inv0 = 1.f / fmaxf(n0, 1e-12f);
    d0x *= inv0; d0y *= inv0; d0z *= inv0;

    float cosv = 1.f;
    if (lane > 0) {
        float4 pn = spos[nb];
        float dx = pn.x - pi.x, dy = pn.y - pi.y, dz = pn.z - pi.z;
        float nrm = sqrtf(dx*dx + dy*dy + dz*dz);
        float inv = 1.f / fmaxf(nrm, 1e-12f);
        cosv = (dx*d0x + dy*d0y + dz*d0z) * inv;
    }
    const float gb   = fmaxf(dist * Spos, 0.f) * mk;
    const float gate = 1.f / (1.f + __expf(-gb));

    float G = gate;
    #pragma unroll
    for (int o = 16; o; o >>= 1) G += __shfl_xor_sync(FULLM, G, o);

    // theta: f = lane*4 + c
    g_X[((size_t)b*NN + i)*XF + 128 + lane*4 + c] = cosv * mk;
    pair[lane] = ((ull)__float_as_uint(gate) << 32) | (unsigned)nb;
    Gout = G; mkout = mk;
}

// ---------------------------------------------------------------------------
// Kernel 1 v10 (unchanged): 2 rows/warp threshold select + folded gather.
// ---------------------------------------------------------------------------
__global__ __launch_bounds__(512, 3) void knn_kernel(
    const float* __restrict__ pos, const float* __restrict__ node_fea,
    const float* __restrict__ node_mask,
    const float* __restrict__ rw1, const float* __restrict__ rw2,
    const float* __restrict__ aw)
{
    extern __shared__ char sm1[];
    float4* spos = (float4*)sm1;                       // 32KB
    ull*    srow = (ull*)(sm1 + NN*16);                // 32 rows x 64 = 16KB
    __shared__ int   scnt[32];
    __shared__ float sSpos;

    const int tid  = threadIdx.x;
    const int warp = tid >> 5;
    const int lane = tid & 31;
    const int slice = blockIdx.y;          // b*C + c
    const int b     = slice >> 2;
    const int c     = slice & 3;
    const float* p  = pos + (size_t)slice * NN * 3;
    const float* nf = node_fea + (size_t)slice * NN * DD;

    for (int j = tid; j < NN; j += 512) {
        float x = p[3*j], y = p[3*j+1], z = p[3*j+2];
        float q = fmaf(z, z, fmaf(y, y, x*x));
        spos[j] = make_float4(x, y, z, q);
    }

    // fold the aw transpose into one knn block (gemm runs after knn)
    if (blockIdx.x == 0 && slice == 0) {
        for (int idx = tid; idx < 128*MM; idx += 512) {
            int f = idx >> 6, m = idx & 63;
            g_awT[idx] = aw[m*128 + f];
        }
    }

    // gate MLP collapses: relu(sum_m relu(d*w1)*w2) = relu(d*Spos) for d>=0
    if (tid < 32) {
        float a1 = rw1[tid],    w1v = rw2[tid];
        float a2 = rw1[tid+32], w2v = rw2[tid+32];
        float sp = fmaf(fmaxf(a1, 0.f), w1v, fmaxf(a2, 0.f) * w2v);
        #pragma unroll
        for (int o = 16; o; o >>= 1) sp += __shfl_xor_sync(FULLM, sp, o);
        if (tid == 0) sSpos = sp;
    }
    __syncthreads();

    const int iA = blockIdx.x * 32 + warp * 2;
    const int iB = iA + 1;
    const float4 piA = spos[iA];
    const float4 piB = spos[iB];

    // pass 1: per-lane two smallest s = -2*dot + q_j (order == d order)
    float a0 = INFINITY, a1 = INFINITY;
    float b0 = INFINITY, b1 = INFINITY;
    #pragma unroll 4
    for (int t = 0; t < 64; t++) {
        float4 pj = spos[t*32 + lane];
        float dotA = fmaf(piA.z, pj.z, fmaf(piA.y, pj.y, piA.x * pj.x));
        float sA   = fmaf(-2.f, dotA, pj.w);
        float tA = fmaxf(a0, sA); a0 = fminf(a0, sA); a1 = fminf(a1, tA);
        float dotB = fmaf(piB.z, pj.z, fmaf(piB.y, pj.y, piB.x * pj.x));
        float sB   = fmaf(-2.f, dotB, pj.w);
        float tB = fmaxf(b0, sB); b0 = fminf(b0, sB); b1 = fminf(b1, tB);
    }

    // bitonic sort 64 heads per row (2 rows interleaved); T = rank 32
    float TA, TB;
    {
        float vA0 = a0, vA1 = a1, vB0 = b0, vB1 = b1;
        #pragma unroll
        for (int k = 2; k <= 32; k <<= 1) {
            #pragma unroll
            for (int j = k >> 1; j > 0; j >>= 1) {
                bool up0 = ((lane & k) == 0);
                bool up1 = (((lane + 32) & k) == 0);
                vA0 = cexf(vA0, j, up0, lane);
                vA1 = cexf(vA1, j, up1, lane);
                vB0 = cexf(vB0, j, up0, lane);
                vB1 = cexf(vB1, j, up1, lane);
            }
        }
        { float lo = fminf(vA0, vA1), hi = fmaxf(vA0, vA1); vA0 = lo; vA1 = hi; }
        { float lo = fminf(vB0, vB1), hi = fmaxf(vB0, vB1); vB0 = lo; vB1 = hi; }
        #pragma unroll
        for (int j = 16; j > 0; j >>= 1) {
            vA0 = cexf(vA0, j, true, lane);
            vA1 = cexf(vA1, j, true, lane);
            vB0 = cexf(vB0, j, true, lane);
            vB1 = cexf(vB1, j, true, lane);
        }
        TA = __shfl_sync(FULLM, vA1, 0);
        TB = __shfl_sync(FULLM, vB1, 0);
    }

    // init survivor buffers
    ull* rowA = srow + (warp*2    ) * 64;
    ull* rowB = srow + (warp*2 + 1) * 64;
    if (lane == 0) { scnt[warp*2] = 0; scnt[warp*2+1] = 0; }
    rowA[lane] = INF64; rowA[lane+32] = INF64;
    rowB[lane] = INF64; rowB[lane+32] = INF64;
    __syncwarp();

    // pass 2: compact survivors (s <= T); key stores d = max(s + q_i, 0)
    #pragma unroll 4
    for (int t = 0; t < 64; t++) {
        const int j = t*32 + lane;
        float4 pj = spos[j];
        float dotA = fmaf(piA.z, pj.z, fmaf(piA.y, pj.y, piA.x * pj.x));
        float sA   = fmaf(-2.f, dotA, pj.w);
        if (sA <= TA) {
            unsigned u = __float_as_uint(fmaxf(sA + piA.w, 0.f));
            int idx = atomicAdd(&scnt[warp*2], 1);
            if (idx < 64) rowA[idx] = ((ull)u << 32) | (unsigned)j;
        }
        float dotB = fmaf(piB.z, pj.z, fmaf(piB.y, pj.y, piB.x * pj.x));
        float sB   = fmaf(-2.f, dotB, pj.w);
        if (sB <= TB) {
            unsigned u = __float_as_uint(fmaxf(sB + piB.w, 0.f));
            int idx = atomicAdd(&scnt[warp*2+1], 1);
            if (idx < 64) rowB[idx] = ((ull)u << 32) | (unsigned)j;
        }
    }
    __syncwarp();

    unsigned nbdA, nbdB; int nbjA, nbjB;
    select_row(iA, spos, rowA, scnt[warp*2],   lane, nbdA, nbjA);
    select_row(iB, spos, rowB, scnt[warp*2+1], lane, nbdB, nbjB);

    // epilogue: theta + gate, stash pairs, fold the feature gather
    const float Spos = sSpos;
    float GA, mkA, GB, mkB;
    emit_stash(c, b, iA, nbdA, nbjA, Spos, node_mask, spos, lane, rowA, GA, mkA);
    emit_stash(c, b, iB, nbdB, nbjB, Spos, node_mask, spos, lane, rowB, GB, mkB);
    __syncwarp();

    {
        const int row = lane >> 4, t = lane & 15;
        const int i   = row ? iB : iA;
        const ull* pr = row ? rowB : rowA;
        float acc = 0.f;
        #pragma unroll 8
        for (int k = 0; k < KK; k++) {
            ull pk = pr[k];
            float g = __uint_as_float((unsigned)(pk >> 32));
            int  nb = (int)(unsigned)pk;
            acc = fmaf(g, __ldg(nf + nb*DD + t), acc);
        }
        const float G  = row ? GB : GA;
        const float mk = row ? mkB : mkA;
        float selfv = __ldg(nf + (size_t)i*DD + t);
        float* gx = g_X + ((size_t)b*NN + i)*XF + c*32;
        gx[t]      = G * mk * selfv;   // self block
        gx[16 + t] = acc * mk;         // neighbor block
    }
}

// ---------------------------------------------------------------------------
// Kernel 2 v2: GEMM with warp-broadcast weights. Block = 64 n x 64 m
// (256 thr, 8 warps; warp -> 8 m's, lane -> 2 n's). Grid 128 = one wave.
// Weight LDS are warp-broadcast (1 wavefront vs 4). smem 131KB.
// ---------------------------------------------------------------------------
#define GX_PIT 66
#define GEMM_SMEM ((16384 + 256*GX_PIT) * 4)

__global__ __launch_bounds__(256) void gemm_kernel(
    const float* __restrict__ sw, const float* __restrict__ node_mask,
    float* __restrict__ out)
{
    extern __shared__ float sm[];
    float* sW = sm;                        // [256 f][64 m]
    float* sX = sm + 16384;                // [256 f][n pitch 66]

    const int tid = threadIdx.x;
    const int b   = blockIdx.x >> 5;       // 32 blocks per batch
    const int n0  = (blockIdx.x & 31) * 64;

    for (int idx = tid; idx < 16384; idx += 256)
        sW[idx] = (idx < 8192) ? sw[idx] : g_awT[idx - 8192];

    for (int idx = tid; idx < 4096; idx += 256) {
        int fq = idx & 63, n = idx >> 6;
        float4 v = *(const float4*)(g_X + ((size_t)b*NN + n0 + n)*XF + fq*4);
        int f = fq * 4;
        sX[(f+0)*GX_PIT + n] = v.x;  sX[(f+1)*GX_PIT + n] = v.y;
        sX[(f+2)*GX_PIT + n] = v.z;  sX[(f+3)*GX_PIT + n] = v.w;
    }
    __syncthreads();

    const int warp = tid >> 5;
    const int lane = tid & 31;
    const int m0   = warp * 8;             // warp-uniform -> broadcast LDS
    const int n    = lane * 2;

    float acc[8][2];
    #pragma unroll
    for (int a = 0; a < 8; a++) { acc[a][0] = 0.f; acc[a][1] = 0.f; }

    #pragma unroll 4
    for (int f = 0; f < XF; f++) {
        float4 wA = *(const float4*)&sW[f*64 + m0];      // broadcast
        float4 wB = *(const float4*)&sW[f*64 + m0 + 4];  // broadcast
        float2 x  = *(const float2*)&sX[f*GX_PIT + n];
        acc[0][0] = fmaf(wA.x, x.x, acc[0][0]); acc[0][1] = fmaf(wA.x, x.y, acc[0][1]);
        acc[1][0] = fmaf(wA.y, x.x, acc[1][0]); acc[1][1] = fmaf(wA.y, x.y, acc[1][1]);
        acc[2][0] = fmaf(wA.z, x.x, acc[2][0]); acc[2][1] = fmaf(wA.z, x.y, acc[2][1]);
        acc[3][0] = fmaf(wA.w, x.x, acc[3][0]); acc[3][1] = fmaf(wA.w, x.y, acc[3][1]);
        acc[4][0] = fmaf(wB.x, x.x, acc[4][0]); acc[4][1] = fmaf(wB.x, x.y, acc[4][1]);
        acc[5][0] = fmaf(wB.y, x.x, acc[5][0]); acc[5][1] = fmaf(wB.y, x.y, acc[5][1]);
        acc[6][0] = fmaf(wB.z, x.x, acc[6][0]); acc[6][1] = fmaf(wB.z, x.y, acc[6][1]);
        acc[7][0] = fmaf(wB.w, x.x, acc[7][0]); acc[7][1] = fmaf(wB.w, x.y, acc[7][1]);
    }

    const float mk0 = node_mask[b*NN + n0 + n];
    const float mk1 = node_mask[b*NN + n0 + n + 1];
    #pragma unroll
    for (int a = 0; a < 8; a++) {
        float v0 = acc[a][0], v1 = acc[a][1];
        v0 = (v0 >= 0.f) ? v0 : 0.01f*v0;
        v1 = (v1 >= 0.f) ? v1 : 0.01f*v1;
        float2 o2 = make_float2(v0*mk0, v1*mk1);
        *(float2*)&out[((size_t)b*MM + m0 + a)*NN + n0 + n] = o2;
    }
}

// ---------------------------------------------------------------------------
extern "C" void kernel_launch(void* const* d_in, const int* in_sizes, int n_in,
                              void* d_out, int out_size)
{
    const float* pos       = (const float*)d_in[0];
    const float* node_fea  = (const float*)d_in[1];
    const float* node_mask = (const float*)d_in[2];
    const float* aw        = (const float*)d_in[3];
    const float* sw        = (const float*)d_in[4];
    const float* rw1       = (const float*)d_in[5];
    const float* rw2       = (const float*)d_in[6];
    float* out = (float*)d_out;

    const int smem1 = NN*16 + 32*64*8;     // 49152
    cudaFuncSetAttribute(knn_kernel,
        cudaFuncAttributeMaxDynamicSharedMemorySize, smem1);
    cudaFuncSetAttribute(gemm_kernel,
        cudaFuncAttributeMaxDynamicSharedMemorySize, GEMM_SMEM);

    knn_kernel<<<dim3(NN/32, BSZ*CC), 512, smem1>>>(
        pos, node_fea, node_mask, rw1, rw2, aw);
    gemm_kernel<<<BSZ*(NN/64), 256, GEMM_SMEM>>>(sw, node_mask, out);
}